// round 12
// baseline (speedup 1.0000x reference)
#include <cuda_runtime.h>
#include <cuda_fp16.h>
#include <math.h>
#include <stdint.h>

#define DM  256
#define SEQ 2304       // 48*48
#define NB  16

__device__ __half g_Q[NB * SEQ * DM];
__device__ __half g_K[NB * SEQ * DM];
__device__ __half g_V[NB * SEQ * DM];
__device__ __half g_W16[3 * DM * DM];

// ---------------------------------------------------------------------------
// helpers
// ---------------------------------------------------------------------------
__device__ __forceinline__ uint32_t smem_u32(const void* p) {
    uint32_t a;
    asm("{ .reg .u64 t; cvta.to.shared.u64 t, %1; cvt.u32.u64 %0, t; }"
        : "=r"(a) : "l"(p));
    return a;
}
__device__ __forceinline__ void ldsm4(uint32_t* r, uint32_t addr) {
    asm volatile("ldmatrix.sync.aligned.m8n8.x4.shared.b16 {%0,%1,%2,%3}, [%4];"
        : "=r"(r[0]), "=r"(r[1]), "=r"(r[2]), "=r"(r[3]) : "r"(addr));
}
__device__ __forceinline__ void ldsm4t(uint32_t* r, uint32_t addr) {
    asm volatile("ldmatrix.sync.aligned.m8n8.x4.trans.shared.b16 {%0,%1,%2,%3}, [%4];"
        : "=r"(r[0]), "=r"(r[1]), "=r"(r[2]), "=r"(r[3]) : "r"(addr));
}
__device__ __forceinline__ void mma16816(float* c, const uint32_t* a,
                                         uint32_t b0, uint32_t b1) {
    asm volatile(
        "mma.sync.aligned.m16n8k16.row.col.f32.f16.f16.f32 "
        "{%0,%1,%2,%3},{%4,%5,%6,%7},{%8,%9},{%0,%1,%2,%3};"
        : "+f"(c[0]), "+f"(c[1]), "+f"(c[2]), "+f"(c[3])
        : "r"(a[0]), "r"(a[1]), "r"(a[2]), "r"(a[3]), "r"(b0), "r"(b1));
}
__device__ __forceinline__ uint32_t pack_h2(float lo, float hi) {
    uint32_t r;
    asm("cvt.rn.f16x2.f32 %0, %1, %2;" : "=r"(r) : "f"(hi), "f"(lo));
    return r;
}
#define CP_ASYNC16(dst, src) \
    asm volatile("cp.async.cg.shared.global [%0], [%1], 16;" \
                 :: "r"(dst), "l"(src) : "memory")
#define CP_COMMIT() asm volatile("cp.async.commit_group;" ::: "memory")
#define CP_WAIT0()  asm volatile("cp.async.wait_group 0;" ::: "memory")
#define CP_WAIT1()  asm volatile("cp.async.wait_group 1;" ::: "memory")

#define ASTR 528                        // bytes per smem row (256h + 8h pad)

// ---------------------------------------------------------------------------
// W pre-convert (one-time)
// ---------------------------------------------------------------------------
__global__ __launch_bounds__(256) void wconv(
    const float* __restrict__ wq, const float* __restrict__ wk,
    const float* __restrict__ wv)
{
    int i4 = (blockIdx.x * 256 + threadIdx.x) * 4;
    int wsel = i4 >> 16;
    int off  = i4 & 65535;
    const float* src = (wsel == 0) ? wq : (wsel == 1) ? wk : wv;
    float4 v = *(const float4*)(src + off);
    uint2 u;
    u.x = pack_h2(v.x, v.y);
    u.y = pack_h2(v.z, v.w);
    *(uint2*)(g_W16 + i4) = u;
}

// ---------------------------------------------------------------------------
// Fused QKV v3 (R9, verified ~55us)
// ---------------------------------------------------------------------------
#define QA  0
#define QW0 (128 * ASTR)
#define QW1 (QW0 + 128 * ASTR)
#define QBIA (QW1 + 128 * ASTR)
#define QKV_SMEM (QBIA + 3072)

__global__ __launch_bounds__(256, 1) void qkv_fused3(
    const float* __restrict__ x,  const float* __restrict__ pos,
    const float* __restrict__ bq, const float* __restrict__ bk,
    const float* __restrict__ bv)
{
    extern __shared__ char smem[];
    const uint32_t sb = smem_u32(smem);
    const int t = threadIdx.x, w = t >> 5, lane = t & 31;
    const int gq = lane >> 2, tg = lane & 3;
    const int i8 = lane & 7, s1 = (lane >> 3) & 1, s2 = (lane >> 4) & 1;
    const int q4 = lane >> 3;

    const int m0 = blockIdx.x * 128;
    const int sbase = m0 % SEQ;

    {
        const char* Wsrc = (const char*)g_W16;
        #pragma unroll
        for (int p = 0; p < 16; p++) {
            int q = p * 256 + t;
            int row = q >> 5, gr = q & 31;
            CP_ASYNC16(sb + QW0 + row * ASTR + gr * 16, Wsrc + row * 512 + gr * 16);
        }
        CP_COMMIT();
    }

    if (t < 192) {
        const float* src = (t < 64) ? bq : (t < 128) ? bk : bv;
        int off = (t & 63) * 4;
        *(float4*)(smem + QBIA + (t >> 6) * 1024 + off * 4) =
            *(const float4*)(src + off);
    }

    #pragma unroll
    for (int p = 0; p < 32; p++) {
        int fid = p * 256 + t;
        int row = fid >> 6, c4 = fid & 63;
        float4 xa = *(const float4*)(x   + (size_t)(m0 + row) * DM + c4 * 4);
        float4 pa = *(const float4*)(pos + (size_t)(sbase + row) * DM + c4 * 4);
        uint2 u;
        u.x = pack_h2(xa.x + pa.x, xa.y + pa.y);
        u.y = pack_h2(xa.z + pa.z, xa.w + pa.w);
        *(uint2*)(smem + QA + row * ASTR + c4 * 8) = u;
    }

    const int wm2 = w & 1, wn2 = w >> 1;
    const uint32_t abase = sb + QA + (64 * wm2 + i8 + s1 * 8) * ASTR + s2 * 16;
    const uint32_t wb_lane = (uint32_t)(((q4 & 1) * 8 + i8) * ASTR + (q4 >> 1) * 16
                                        + 128 * wn2);

    __half* Os[3];
    Os[0] = g_Q; Os[1] = g_K; Os[2] = g_V;

    float acc[4][8][4] = {};

    #pragma unroll 1
    for (int c = 0; c < 6; c++) {
        const int wsel = c >> 1, kc = c & 1;
        const uint32_t wbuf = sb + ((c & 1) ? QW1 : QW0);

        if (c + 1 < 6) {
            const int nc = c + 1;
            const char* Wsrc = (const char*)(g_W16 + (nc >> 1) * 65536
                                             + (nc & 1) * 128 * DM);
            const uint32_t wdst = sb + ((nc & 1) ? QW1 : QW0);
            #pragma unroll
            for (int p = 0; p < 16; p++) {
                int q = p * 256 + t;
                int row = q >> 5, gr = q & 31;
                CP_ASYNC16(wdst + row * ASTR + gr * 16, Wsrc + row * 512 + gr * 16);
            }
            CP_COMMIT();
            CP_WAIT1();
        } else {
            CP_WAIT0();
        }
        __syncthreads();

        #pragma unroll
        for (int kk = 0; kk < 8; kk++) {
            uint32_t a[4][4];
            #pragma unroll
            for (int mi = 0; mi < 4; mi++)
                ldsm4(a[mi], abase + mi * 16 * ASTR + kc * 256 + kk * 32);
            #pragma unroll
            for (int np = 0; np < 4; np++) {
                uint32_t bb[4];
                ldsm4t(bb, wbuf + (uint32_t)(kk * 16) * ASTR + wb_lane + np * 32);
                #pragma unroll
                for (int mi = 0; mi < 4; mi++) {
                    mma16816(acc[mi][2 * np],     a[mi], bb[0], bb[1]);
                    mma16816(acc[mi][2 * np + 1], a[mi], bb[2], bb[3]);
                }
            }
        }

        if (kc == 1) {
            const float* bias = (const float*)(smem + QBIA + wsel * 1024);
            __half* outp = Os[wsel];
            #pragma unroll
            for (int mi = 0; mi < 4; mi++) {
                int r0 = 64 * wm2 + 16 * mi + gq;
                #pragma unroll
                for (int nt = 0; nt < 8; nt++) {
                    int col = 64 * wn2 + 8 * nt + 2 * tg;
                    float2 bv2 = *(const float2*)(bias + col);
                    *(uint32_t*)(outp + (size_t)(m0 + r0) * DM + col) =
                        pack_h2(acc[mi][nt][0] + bv2.x, acc[mi][nt][1] + bv2.y);
                    *(uint32_t*)(outp + (size_t)(m0 + r0 + 8) * DM + col) =
                        pack_h2(acc[mi][nt][2] + bv2.x, acc[mi][nt][3] + bv2.y);
                }
            }
            #pragma unroll
            for (int mi = 0; mi < 4; mi++)
                #pragma unroll
                for (int nt = 0; nt < 8; nt++)
                    #pragma unroll
                    for (int k2 = 0; k2 < 4; k2++)
                        acc[mi][nt][k2] = 0.0f;
        }
        __syncthreads();
    }
}

// ---------------------------------------------------------------------------
// Attention v7 (software-pipelined): CTA = 128 q-rows, 256 thr, TOK = 32.
// Iteration i: [barrier] -> O(i-1) + S(i) back-to-back HMMA -> exp -> P(i).
// One barrier per chunk; tensor never idles through softmax of chunk i
// because O(i-1) is ready at iteration entry.
// S-phase: warp w owns rows 16w..+15 x all 32 tokens (rowsum warp-local).
// O-phase: warp -> rows 64*(w&1)..+63, d-slice 64*(w>>1)..+63.
// K, V, P all double-buffered.
// ---------------------------------------------------------------------------
#define TOK 32
#define NCHUNK (SEQ / TOK)       // 72
#define PSTR 80                  // P row stride (32h=64B + 16 pad)

#define AQ  0                        // Q [128][528]     67584
#define AK0 (128 * ASTR)             // K/V bufs [32][528] x4
#define AK1 (AK0 + 32 * ASTR)
#define AV0 (AK1 + 32 * ASTR)
#define AV1 (AV0 + 32 * ASTR)
#define AP0 (AV1 + 32 * ASTR)        // P bufs [128][80] x2
#define AP1 (AP0 + 128 * PSTR)
#define ARS (AP1 + 128 * PSTR)       // rowsum [128] f32
#define ATT_SMEM (ARS + 512)         // 156672

__global__ __launch_bounds__(256, 1) void attn_pipe(float* __restrict__ out)
{
    extern __shared__ char smem[];
    const uint32_t sb = smem_u32(smem);
    const int t = threadIdx.x, w = t >> 5, lane = t & 31;
    const int g = lane >> 2, tg = lane & 3;
    const int i8 = lane & 7, s1 = (lane >> 3) & 1, s2 = (lane >> 4) & 1;
    const int q4 = lane >> 3;

    const int qt = blockIdx.x, b = blockIdx.y;
    const __half* Qg = g_Q + ((size_t)b * SEQ + qt * 128) * DM;
    const __half* Kg = g_K + (size_t)b * SEQ * DM;
    const __half* Vg = g_V + (size_t)b * SEQ * DM;

    // prologue: Q tile + K(0)
    #pragma unroll
    for (int p = 0; p < 16; p++) {
        int q = p * 256 + t;
        int row = q >> 5, gr = q & 31;
        CP_ASYNC16(sb + AQ + row * ASTR + gr * 16,
                   (const char*)Qg + row * 512 + gr * 16);
    }
    #pragma unroll
    for (int p = 0; p < 4; p++) {
        int q = p * 256 + t;
        int row = q >> 5, gr = q & 31;
        CP_ASYNC16(sb + AK0 + row * ASTR + gr * 16,
                   (const char*)Kg + row * 512 + gr * 16);
    }
    CP_COMMIT();

    // S-phase: warp w -> rows 16w..+15, all 32 tokens
    const uint32_t qa_base = sb + AQ + (16 * w + i8 + s1 * 8) * ASTR + s2 * 16;
    const uint32_t kb_lane = (uint32_t)(((q4 >> 1) * 8 + i8) * ASTR + (q4 & 1) * 16);
    // O-phase: rows 64*wm2..+63, d-slice 64*wn2..+63
    const int wm2 = w & 1, wn2 = w >> 1;
    const uint32_t vb_lane = (uint32_t)(((q4 & 1) * 8 + i8) * ASTR + (q4 >> 1) * 16
                                        + 128 * wn2);
    const uint32_t pa_lane = (uint32_t)((64 * wm2 + i8 + s1 * 8) * PSTR + s2 * 16);

    const int prow0 = 16 * w + g;       // S-phase / rowsum rows
    const float scale = 0.0625f;

    float oc[4][8][4] = {};
    float rs0 = 0.0f, rs1 = 0.0f;

    // ---- step 0: S(0), exp -> P(0); prefetch {K(1), V(0)} ----
    CP_WAIT0();
    __syncthreads();
    {
        const __half* Kt = Kg + (size_t)TOK * DM;   // K(1)
        #pragma unroll
        for (int p = 0; p < 4; p++) {
            int q = p * 256 + t;
            int row = q >> 5, gr = q & 31;
            CP_ASYNC16(sb + AK1 + row * ASTR + gr * 16,
                       (const char*)Kt + row * 512 + gr * 16);
            CP_ASYNC16(sb + AV0 + row * ASTR + gr * 16,
                       (const char*)Vg + row * 512 + gr * 16);
        }
        CP_COMMIT();

        float sc[4][4] = {};
        #pragma unroll
        for (int kk = 0; kk < 16; kk++) {
            uint32_t a[4];
            ldsm4(a, qa_base + kk * 32);
            uint32_t bb[4];
            ldsm4(bb, sb + AK0 + kb_lane + kk * 32);
            mma16816(sc[0], a, bb[0], bb[1]);
            mma16816(sc[1], a, bb[2], bb[3]);
            ldsm4(bb, sb + AK0 + 16 * ASTR + kb_lane + kk * 32);
            mma16816(sc[2], a, bb[0], bb[1]);
            mma16816(sc[3], a, bb[2], bb[3]);
        }
        char* pw = smem + AP0 + prow0 * PSTR + tg * 4;
        #pragma unroll
        for (int nt = 0; nt < 4; nt++) {
            float p00 = __expf(sc[nt][0] * scale);
            float p01 = __expf(sc[nt][1] * scale);
            float p10 = __expf(sc[nt][2] * scale);
            float p11 = __expf(sc[nt][3] * scale);
            rs0 += p00 + p01;
            rs1 += p10 + p11;
            *(uint32_t*)(pw + nt * 16)            = pack_h2(p00, p01);
            *(uint32_t*)(pw + nt * 16 + 8 * PSTR) = pack_h2(p10, p11);
        }
    }

    // ---- main loop i = 1..71: O(i-1) + S(i) + exp->P(i) ----
    #pragma unroll 1
    for (int i = 1; i < NCHUNK; i++) {
        CP_WAIT0();          // {K(i), V(i-1)} landed
        __syncthreads();     // P(i-1) complete; safe to overwrite P(i) buf

        const uint32_t kbuf = sb + ((i & 1) ? AK1 : AK0);
        const uint32_t vbuf = sb + ((i & 1) ? AV0 : AV1);       // V(i-1)
        const uint32_t pbufR = sb + ((i & 1) ? AP0 : AP1);      // P(i-1)
        char* pbufW = smem + ((i & 1) ? AP1 : AP0);             // P(i)

        // prefetch {K(i+1) (if any), V(i)}
        {
            const __half* Vt = Vg + (size_t)i * TOK * DM;
            const uint32_t vdst = sb + ((i & 1) ? AV1 : AV0);
            if (i + 1 < NCHUNK) {
                const __half* Kt = Kg + (size_t)(i + 1) * TOK * DM;
                const uint32_t kdst = sb + (((i + 1) & 1) ? AK1 : AK0);
                #pragma unroll
                for (int p = 0; p < 4; p++) {
                    int q = p * 256 + t;
                    int row = q >> 5, gr = q & 31;
                    CP_ASYNC16(kdst + row * ASTR + gr * 16,
                               (const char*)Kt + row * 512 + gr * 16);
                    CP_ASYNC16(vdst + row * ASTR + gr * 16,
                               (const char*)Vt + row * 512 + gr * 16);
                }
            } else {
                #pragma unroll
                for (int p = 0; p < 4; p++) {
                    int q = p * 256 + t;
                    int row = q >> 5, gr = q & 31;
                    CP_ASYNC16(vdst + row * ASTR + gr * 16,
                               (const char*)Vt + row * 512 + gr * 16);
                }
            }
            CP_COMMIT();
        }

        // ---- O(i-1) += P(i-1) V(i-1) : 64r x 64d, k=32 ----
        #pragma unroll
        for (int kk2 = 0; kk2 < 2; kk2++) {
            uint32_t pa[4][4];
            #pragma unroll
            for (int mi = 0; mi < 4; mi++)
                ldsm4(pa[mi], pbufR + pa_lane + mi * 16 * PSTR + kk2 * 32);
            #pragma unroll
            for (int np = 0; np < 4; np++) {
                uint32_t bb[4];
                ldsm4t(bb, vbuf + (uint32_t)(kk2 * 16) * ASTR + vb_lane + np * 32);
                #pragma unroll
                for (int mi = 0; mi < 4; mi++) {
                    mma16816(oc[mi][2 * np],     pa[mi], bb[0], bb[1]);
                    mma16816(oc[mi][2 * np + 1], pa[mi], bb[2], bb[3]);
                }
            }
        }

        // ---- S(i) = Q K(i)^T : 16r x 32 tok, K-dim 256 ----
        float sc[4][4] = {};
        #pragma unroll
        for (int kk = 0; kk < 16; kk++) {
            uint32_t a[4];
            ldsm4(a, qa_base + kk * 32);
            uint32_t bb[4];
            ldsm4(bb, kbuf + kb_lane + kk * 32);
            mma16816(sc[0], a, bb[0], bb[1]);
            mma16816(sc[1], a, bb[2], bb[3]);
            ldsm4(bb, kbuf + 16 * ASTR + kb_lane + kk * 32);
            mma16816(sc[2], a, bb[0], bb[1]);
            mma16816(sc[3], a, bb[2], bb[3]);
        }

        // ---- exp -> P(i) ----
        char* pw = pbufW + prow0 * PSTR + tg * 4;
        #pragma unroll
        for (int nt = 0; nt < 4; nt++) {
            float p00 = __expf(sc[nt][0] * scale);
            float p01 = __expf(sc[nt][1] * scale);
            float p10 = __expf(sc[nt][2] * scale);
            float p11 = __expf(sc[nt][3] * scale);
            rs0 += p00 + p01;
            rs1 += p10 + p11;
            *(uint32_t*)(pw + nt * 16)            = pack_h2(p00, p01);
            *(uint32_t*)(pw + nt * 16 + 8 * PSTR) = pack_h2(p10, p11);
        }
    }

    // ---- final: O(71) with P(71), V(71) (both buf 1) ----
    CP_WAIT0();
    __syncthreads();
    {
        const uint32_t vbuf = sb + AV1;          // V(71): 71&1 -> AV1
        const uint32_t pbufR = sb + AP1;         // P(71)
        #pragma unroll
        for (int kk2 = 0; kk2 < 2; kk2++) {
            uint32_t pa[4][4];
            #pragma unroll
            for (int mi = 0; mi < 4; mi++)
                ldsm4(pa[mi], pbufR + pa_lane + mi * 16 * PSTR + kk2 * 32);
            #pragma unroll
            for (int np = 0; np < 4; np++) {
                uint32_t bb[4];
                ldsm4t(bb, vbuf + (uint32_t)(kk2 * 16) * ASTR + vb_lane + np * 32);
                #pragma unroll
                for (int mi = 0; mi < 4; mi++) {
                    mma16816(oc[mi][2 * np],     pa[mi], bb[0], bb[1]);
                    mma16816(oc[mi][2 * np + 1], pa[mi], bb[2], bb[3]);
                }
            }
        }
    }

    // ---- rowsum finalize (warp-local rows) ----
    rs0 += __shfl_xor_sync(0xffffffffu, rs0, 1);
    rs0 += __shfl_xor_sync(0xffffffffu, rs0, 2);
    rs1 += __shfl_xor_sync(0xffffffffu, rs1, 1);
    rs1 += __shfl_xor_sync(0xffffffffu, rs1, 2);
    float* rsum = (float*)(smem + ARS);
    if (tg == 0) {
        rsum[prow0]     = rs0;
        rsum[prow0 + 8] = rs1;
    }
    __syncthreads();

    // ---- output: rows 64*wm2..+63, cols 64*wn2..+63 ----
    float* ob = out + ((size_t)b * SEQ + qt * 128) * DM;
    #pragma unroll
    for (int mi = 0; mi < 4; mi++) {
        int r0 = 64 * wm2 + 16 * mi + g;
        int r1 = r0 + 8;
        float inv0 = 1.0f / rsum[r0];
        float inv1 = 1.0f / rsum[r1];
        #pragma unroll
        for (int nt = 0; nt < 8; nt++) {
            int col = 64 * wn2 + 8 * nt + 2 * tg;
            *(float2*)(ob + (size_t)r0 * DM + col) =
                make_float2(oc[mi][nt][0] * inv0, oc[mi][nt][1] * inv0);
            *(float2*)(ob + (size_t)r1 * DM + col) =
                make_float2(oc[mi][nt][2] * inv1, oc[mi][nt][3] * inv1);
        }
    }
}

extern "C" void kernel_launch(void* const* d_in, const int* in_sizes, int n_in,
                              void* d_out, int out_size)
{
    const float* x   = (const float*)d_in[0];
    const float* wq  = (const float*)d_in[1];
    const float* bq  = (const float*)d_in[2];
    const float* wk  = (const float*)d_in[3];
    const float* bk  = (const float*)d_in[4];
    const float* wv  = (const float*)d_in[5];
    const float* bv  = (const float*)d_in[6];
    const float* pos = (const float*)d_in[7];
    float* out = (float*)d_out;

    cudaFuncSetAttribute(qkv_fused3, cudaFuncAttributeMaxDynamicSharedMemorySize,
                         QKV_SMEM);
    cudaFuncSetAttribute(attn_pipe, cudaFuncAttributeMaxDynamicSharedMemorySize,
                         ATT_SMEM);

    wconv<<<192, 256>>>(wq, wk, wv);
    qkv_fused3<<<(NB * SEQ) / 128, 256, QKV_SMEM>>>(x, pos, bq, bk, bv);
    attn_pipe<<<dim3(SEQ / 128, NB), 256, ATT_SMEM>>>(out);
}

// round 13
// speedup vs baseline: 1.0529x; 1.0529x over previous
#include <cuda_runtime.h>
#include <cuda_fp16.h>
#include <math.h>
#include <stdint.h>

#define DM  256
#define SEQ 2304       // 48*48
#define NB  16

__device__ __half g_Q[NB * SEQ * DM];
__device__ __half g_K[NB * SEQ * DM];
__device__ __half g_V[NB * SEQ * DM];
__device__ __half g_W16[3 * DM * DM];

// ---------------------------------------------------------------------------
// helpers
// ---------------------------------------------------------------------------
__device__ __forceinline__ uint32_t smem_u32(const void* p) {
    uint32_t a;
    asm("{ .reg .u64 t; cvta.to.shared.u64 t, %1; cvt.u32.u64 %0, t; }"
        : "=r"(a) : "l"(p));
    return a;
}
__device__ __forceinline__ void ldsm4(uint32_t* r, uint32_t addr) {
    asm volatile("ldmatrix.sync.aligned.m8n8.x4.shared.b16 {%0,%1,%2,%3}, [%4];"
        : "=r"(r[0]), "=r"(r[1]), "=r"(r[2]), "=r"(r[3]) : "r"(addr));
}
__device__ __forceinline__ void ldsm4t(uint32_t* r, uint32_t addr) {
    asm volatile("ldmatrix.sync.aligned.m8n8.x4.trans.shared.b16 {%0,%1,%2,%3}, [%4];"
        : "=r"(r[0]), "=r"(r[1]), "=r"(r[2]), "=r"(r[3]) : "r"(addr));
}
__device__ __forceinline__ void ldsm2t(uint32_t& r0, uint32_t& r1, uint32_t addr) {
    asm volatile("ldmatrix.sync.aligned.m8n8.x2.trans.shared.b16 {%0,%1}, [%2];"
        : "=r"(r0), "=r"(r1) : "r"(addr));
}
__device__ __forceinline__ void mma16816(float* c, const uint32_t* a,
                                         uint32_t b0, uint32_t b1) {
    asm volatile(
        "mma.sync.aligned.m16n8k16.row.col.f32.f16.f16.f32 "
        "{%0,%1,%2,%3},{%4,%5,%6,%7},{%8,%9},{%0,%1,%2,%3};"
        : "+f"(c[0]), "+f"(c[1]), "+f"(c[2]), "+f"(c[3])
        : "r"(a[0]), "r"(a[1]), "r"(a[2]), "r"(a[3]), "r"(b0), "r"(b1));
}
__device__ __forceinline__ uint32_t pack_h2(float lo, float hi) {
    uint32_t r;
    asm("cvt.rn.f16x2.f32 %0, %1, %2;" : "=r"(r) : "f"(hi), "f"(lo));
    return r;
}
#define CP_ASYNC16(dst, src) \
    asm volatile("cp.async.cg.shared.global [%0], [%1], 16;" \
                 :: "r"(dst), "l"(src) : "memory")
#define CP_COMMIT() asm volatile("cp.async.commit_group;" ::: "memory")
#define CP_WAIT0()  asm volatile("cp.async.wait_group 0;" ::: "memory")
#define CP_WAIT1()  asm volatile("cp.async.wait_group 1;" ::: "memory")

#define ASTR 528                        // bytes per smem row (256h + 8h pad)

// ---------------------------------------------------------------------------
// W pre-convert (one-time)
// ---------------------------------------------------------------------------
__global__ __launch_bounds__(256) void wconv(
    const float* __restrict__ wq, const float* __restrict__ wk,
    const float* __restrict__ wv)
{
    int i4 = (blockIdx.x * 256 + threadIdx.x) * 4;
    int wsel = i4 >> 16;
    int off  = i4 & 65535;
    const float* src = (wsel == 0) ? wq : (wsel == 1) ? wk : wv;
    float4 v = *(const float4*)(src + off);
    uint2 u;
    u.x = pack_h2(v.x, v.y);
    u.y = pack_h2(v.z, v.w);
    *(uint2*)(g_W16 + i4) = u;
}

// ---------------------------------------------------------------------------
// Fused QKV v3 (R9, verified)
// ---------------------------------------------------------------------------
#define QA  0
#define QW0 (128 * ASTR)
#define QW1 (QW0 + 128 * ASTR)
#define QBIA (QW1 + 128 * ASTR)
#define QKV_SMEM (QBIA + 3072)

__global__ __launch_bounds__(256, 1) void qkv_fused3(
    const float* __restrict__ x,  const float* __restrict__ pos,
    const float* __restrict__ bq, const float* __restrict__ bk,
    const float* __restrict__ bv)
{
    extern __shared__ char smem[];
    const uint32_t sb = smem_u32(smem);
    const int t = threadIdx.x, w = t >> 5, lane = t & 31;
    const int gq = lane >> 2, tg = lane & 3;
    const int i8 = lane & 7, s1 = (lane >> 3) & 1, s2 = (lane >> 4) & 1;
    const int q4 = lane >> 3;

    const int m0 = blockIdx.x * 128;
    const int sbase = m0 % SEQ;

    {
        const char* Wsrc = (const char*)g_W16;
        #pragma unroll
        for (int p = 0; p < 16; p++) {
            int q = p * 256 + t;
            int row = q >> 5, gr = q & 31;
            CP_ASYNC16(sb + QW0 + row * ASTR + gr * 16, Wsrc + row * 512 + gr * 16);
        }
        CP_COMMIT();
    }

    if (t < 192) {
        const float* src = (t < 64) ? bq : (t < 128) ? bk : bv;
        int off = (t & 63) * 4;
        *(float4*)(smem + QBIA + (t >> 6) * 1024 + off * 4) =
            *(const float4*)(src + off);
    }

    #pragma unroll
    for (int p = 0; p < 32; p++) {
        int fid = p * 256 + t;
        int row = fid >> 6, c4 = fid & 63;
        float4 xa = *(const float4*)(x   + (size_t)(m0 + row) * DM + c4 * 4);
        float4 pa = *(const float4*)(pos + (size_t)(sbase + row) * DM + c4 * 4);
        uint2 u;
        u.x = pack_h2(xa.x + pa.x, xa.y + pa.y);
        u.y = pack_h2(xa.z + pa.z, xa.w + pa.w);
        *(uint2*)(smem + QA + row * ASTR + c4 * 8) = u;
    }

    const int wm2 = w & 1, wn2 = w >> 1;
    const uint32_t abase = sb + QA + (64 * wm2 + i8 + s1 * 8) * ASTR + s2 * 16;
    const uint32_t wb_lane = (uint32_t)(((q4 & 1) * 8 + i8) * ASTR + (q4 >> 1) * 16
                                        + 128 * wn2);

    __half* Os[3];
    Os[0] = g_Q; Os[1] = g_K; Os[2] = g_V;

    float acc[4][8][4] = {};

    #pragma unroll 1
    for (int c = 0; c < 6; c++) {
        const int wsel = c >> 1, kc = c & 1;
        const uint32_t wbuf = sb + ((c & 1) ? QW1 : QW0);

        if (c + 1 < 6) {
            const int nc = c + 1;
            const char* Wsrc = (const char*)(g_W16 + (nc >> 1) * 65536
                                             + (nc & 1) * 128 * DM);
            const uint32_t wdst = sb + ((nc & 1) ? QW1 : QW0);
            #pragma unroll
            for (int p = 0; p < 16; p++) {
                int q = p * 256 + t;
                int row = q >> 5, gr = q & 31;
                CP_ASYNC16(wdst + row * ASTR + gr * 16, Wsrc + row * 512 + gr * 16);
            }
            CP_COMMIT();
            CP_WAIT1();
        } else {
            CP_WAIT0();
        }
        __syncthreads();

        #pragma unroll
        for (int kk = 0; kk < 8; kk++) {
            uint32_t a[4][4];
            #pragma unroll
            for (int mi = 0; mi < 4; mi++)
                ldsm4(a[mi], abase + mi * 16 * ASTR + kc * 256 + kk * 32);
            #pragma unroll
            for (int np = 0; np < 4; np++) {
                uint32_t bb[4];
                ldsm4t(bb, wbuf + (uint32_t)(kk * 16) * ASTR + wb_lane + np * 32);
                #pragma unroll
                for (int mi = 0; mi < 4; mi++) {
                    mma16816(acc[mi][2 * np],     a[mi], bb[0], bb[1]);
                    mma16816(acc[mi][2 * np + 1], a[mi], bb[2], bb[3]);
                }
            }
        }

        if (kc == 1) {
            const float* bias = (const float*)(smem + QBIA + wsel * 1024);
            __half* outp = Os[wsel];
            #pragma unroll
            for (int mi = 0; mi < 4; mi++) {
                int r0 = 64 * wm2 + 16 * mi + gq;
                #pragma unroll
                for (int nt = 0; nt < 8; nt++) {
                    int col = 64 * wn2 + 8 * nt + 2 * tg;
                    float2 bv2 = *(const float2*)(bias + col);
                    *(uint32_t*)(outp + (size_t)(m0 + r0) * DM + col) =
                        pack_h2(acc[mi][nt][0] + bv2.x, acc[mi][nt][1] + bv2.y);
                    *(uint32_t*)(outp + (size_t)(m0 + r0 + 8) * DM + col) =
                        pack_h2(acc[mi][nt][2] + bv2.x, acc[mi][nt][3] + bv2.y);
                }
            }
            #pragma unroll
            for (int mi = 0; mi < 4; mi++)
                #pragma unroll
                for (int nt = 0; nt < 8; nt++)
                    #pragma unroll
                    for (int k2 = 0; k2 < 4; k2++)
                        acc[mi][nt][k2] = 0.0f;
        }
        __syncthreads();
    }
}

// ---------------------------------------------------------------------------
// Attention v8: R8 tiling + cross-chunk pipelining at TOK=64.
// Iteration i: [wait+bar] -> prefetch{K(i+1),V(i)} -> O(i-1)+S(i) (256
// contiguous HMMA) -> [bar] -> exp -> P(i). P single-buffered (legal: P(i-1)
// reads all complete at the mid barrier). V prefetch runs one iter behind K.
// S warp tile 32r x 32t (no dup); O warp tile 64r x 64d (R8-proven maps).
// ---------------------------------------------------------------------------
#define TOK 64
#define NCHUNK (SEQ / TOK)       // 36
#define PSTR 144                 // P row stride (64h=128B + 16 pad)

#define AQ  0                        // Q [128][528]       67584
#define AK0 (128 * ASTR)             // K parity-0 [64][528]
#define AK1 (AK0 + 64 * ASTR)        // K parity-1
#define AV0 (AK1 + 64 * ASTR)        // V parity-0
#define AV1 (AV0 + 64 * ASTR)        // V parity-1
#define AP  (AV1 + 64 * ASTR)        // P [128][144]       202752
#define ARS (AP + 128 * PSTR)        // rowsum [128][2]    221184
#define ATT_SMEM (ARS + 1024)        // 222208

__global__ __launch_bounds__(256, 1) void attn_pipe64(float* __restrict__ out)
{
    extern __shared__ char smem[];
    const uint32_t sb = smem_u32(smem);
    const int t = threadIdx.x, w = t >> 5, lane = t & 31;
    const int g = lane >> 2, tg = lane & 3;
    const int i8 = lane & 7, s1 = (lane >> 3) & 1, s2 = (lane >> 4) & 1;
    const int q4 = lane >> 3;

    const int qt = blockIdx.x, b = blockIdx.y;
    const __half* Qg = g_Q + ((size_t)b * SEQ + qt * 128) * DM;
    const __half* Kg = g_K + (size_t)b * SEQ * DM;
    const __half* Vg = g_V + (size_t)b * SEQ * DM;

    // prologue: Q tile + K(0) (parity 0)
    #pragma unroll
    for (int p = 0; p < 16; p++) {
        int q = p * 256 + t;
        int row = q >> 5, gr = q & 31;
        CP_ASYNC16(sb + AQ + row * ASTR + gr * 16,
                   (const char*)Qg + row * 512 + gr * 16);
    }
    #pragma unroll
    for (int p = 0; p < 8; p++) {
        int q = p * 256 + t;
        int row = q >> 5, gr = q & 31;
        CP_ASYNC16(sb + AK0 + row * ASTR + gr * 16,
                   (const char*)Kg + row * 512 + gr * 16);
    }
    CP_COMMIT();

    // S-phase warp tile: rows 32*wm..+31, tokens 32*wn..+31
    const int wm = w & 3, wn = w >> 2;
    // O-phase warp tile: rows 64*wm2..+63, d-cols 64*wn2..+63
    const int wm2 = w & 1, wn2 = w >> 1;

    const uint32_t qa_base = sb + AQ + (32 * wm + i8 + s1 * 8) * ASTR + s2 * 16;
    const uint32_t kb_lane = (uint32_t)(((q4 >> 1) * 8 + i8) * ASTR + (q4 & 1) * 16);
    const uint32_t vb_lane = (uint32_t)(((q4 & 1) * 8 + i8) * ASTR + (q4 >> 1) * 16);
    const uint32_t pa_base = sb + AP + (64 * wm2 + i8 + s1 * 8) * PSTR + s2 * 16;

    float oc[4][8][4] = {};
    float rsp[2][2] = {};
    const float scale = 0.0625f;

    #pragma unroll 1
    for (int i = 0; i < NCHUNK; i++) {
        CP_WAIT0();          // {K(i), V(i-1)} landed
        __syncthreads();     // P(i-1) visible; prior-parity K/V reads done

        const uint32_t kbuf  = sb + ((i & 1) ? AK1 : AK0);       // K(i)
        const uint32_t vread = sb + ((i & 1) ? AV0 : AV1);       // V(i-1)

        // prefetch {K(i+1), V(i)}
        {
            const __half* Vt = Vg + (size_t)i * TOK * DM;
            const uint32_t vdst = sb + ((i & 1) ? AV1 : AV0);    // V(i)
            if (i + 1 < NCHUNK) {
                const __half* Kt = Kg + (size_t)(i + 1) * TOK * DM;
                const uint32_t kdst = sb + (((i + 1) & 1) ? AK1 : AK0);
                #pragma unroll
                for (int p = 0; p < 8; p++) {
                    int q = p * 256 + t;
                    int row = q >> 5, gr = q & 31;
                    CP_ASYNC16(kdst + row * ASTR + gr * 16,
                               (const char*)Kt + row * 512 + gr * 16);
                    CP_ASYNC16(vdst + row * ASTR + gr * 16,
                               (const char*)Vt + row * 512 + gr * 16);
                }
            } else {
                #pragma unroll
                for (int p = 0; p < 8; p++) {
                    int q = p * 256 + t;
                    int row = q >> 5, gr = q & 31;
                    CP_ASYNC16(vdst + row * ASTR + gr * 16,
                               (const char*)Vt + row * 512 + gr * 16);
                }
            }
            CP_COMMIT();
        }

        // ---- O(i-1) += P(i-1) V(i-1) : 64r x 64d, k=64 ----
        if (i > 0) {
            #pragma unroll
            for (int kk2 = 0; kk2 < 4; kk2++) {
                uint32_t pa[4][4];
                #pragma unroll
                for (int mi = 0; mi < 4; mi++)
                    ldsm4(pa[mi], pa_base + mi * 16 * PSTR + kk2 * 32);
                #pragma unroll
                for (int np = 0; np < 4; np++) {
                    uint32_t bb[4];
                    ldsm4t(bb, vread + (uint32_t)(kk2 * 16) * ASTR + vb_lane
                                + 128 * wn2 + np * 32);
                    #pragma unroll
                    for (int mi = 0; mi < 4; mi++) {
                        mma16816(oc[mi][2 * np],     pa[mi], bb[0], bb[1]);
                        mma16816(oc[mi][2 * np + 1], pa[mi], bb[2], bb[3]);
                    }
                }
            }
        }

        // ---- S(i) = Q K(i)^T : 32r x 32t (this warp), K-dim 256 ----
        float sc[2][4][4] = {};
        #pragma unroll
        for (int kk = 0; kk < 16; kk++) {
            uint32_t a0[4], a1[4];
            ldsm4(a0, qa_base + kk * 32);
            ldsm4(a1, qa_base + 16 * ASTR + kk * 32);
            uint32_t bb[4];
            ldsm4(bb, kbuf + (uint32_t)(32 * wn) * ASTR + kb_lane + kk * 32);
            mma16816(sc[0][0], a0, bb[0], bb[1]);
            mma16816(sc[1][0], a1, bb[0], bb[1]);
            mma16816(sc[0][1], a0, bb[2], bb[3]);
            mma16816(sc[1][1], a1, bb[2], bb[3]);
            ldsm4(bb, kbuf + (uint32_t)(32 * wn + 16) * ASTR + kb_lane + kk * 32);
            mma16816(sc[0][2], a0, bb[0], bb[1]);
            mma16816(sc[1][2], a1, bb[0], bb[1]);
            mma16816(sc[0][3], a0, bb[2], bb[3]);
            mma16816(sc[1][3], a1, bb[2], bb[3]);
        }

        __syncthreads();   // all warps done reading P(i-1); safe to overwrite

        // ---- exp -> P(i), accumulate rowsum ----
        #pragma unroll
        for (int mi = 0; mi < 2; mi++) {
            int rowA = 32 * wm + 16 * mi + g;
            char* pw = smem + AP + rowA * PSTR + (16 * wn + tg) * 4;
            #pragma unroll
            for (int nt = 0; nt < 4; nt++) {
                float p00 = __expf(sc[mi][nt][0] * scale);
                float p01 = __expf(sc[mi][nt][1] * scale);
                float p10 = __expf(sc[mi][nt][2] * scale);
                float p11 = __expf(sc[mi][nt][3] * scale);
                rsp[mi][0] += p00 + p01;
                rsp[mi][1] += p10 + p11;
                *(uint32_t*)(pw + nt * 16)            = pack_h2(p00, p01);
                *(uint32_t*)(pw + nt * 16 + 8 * PSTR) = pack_h2(p10, p11);
            }
        }
    }

    // ---- final O(35): V(35) parity 1 -> AV1; P(35) in AP ----
    CP_WAIT0();
    __syncthreads();
    {
        const uint32_t vread = sb + AV1;
        #pragma unroll
        for (int kk2 = 0; kk2 < 4; kk2++) {
            uint32_t pa[4][4];
            #pragma unroll
            for (int mi = 0; mi < 4; mi++)
                ldsm4(pa[mi], pa_base + mi * 16 * PSTR + kk2 * 32);
            #pragma unroll
            for (int np = 0; np < 4; np++) {
                uint32_t bb[4];
                ldsm4t(bb, vread + (uint32_t)(kk2 * 16) * ASTR + vb_lane
                            + 128 * wn2 + np * 32);
                #pragma unroll
                for (int mi = 0; mi < 4; mi++) {
                    mma16816(oc[mi][2 * np],     pa[mi], bb[0], bb[1]);
                    mma16816(oc[mi][2 * np + 1], pa[mi], bb[2], bb[3]);
                }
            }
        }
    }

    // ---- rowsum finalize (R8 epilogue) ----
    float* rs = (float*)(smem + ARS);
    #pragma unroll
    for (int mi = 0; mi < 2; mi++)
        #pragma unroll
        for (int h = 0; h < 2; h++) {
            float v = rsp[mi][h];
            v += __shfl_xor_sync(0xffffffffu, v, 1);
            v += __shfl_xor_sync(0xffffffffu, v, 2);
            if (tg == 0) rs[(32 * wm + 16 * mi + g + 8 * h) * 2 + wn] = v;
        }
    __syncthreads();

    // ---- output ----
    float* ob = out + ((size_t)b * SEQ + qt * 128) * DM;
    #pragma unroll
    for (int mi = 0; mi < 4; mi++) {
        int r0 = 64 * wm2 + 16 * mi + g;
        float inv0 = 1.0f / (rs[r0 * 2] + rs[r0 * 2 + 1]);
        float inv1 = 1.0f / (rs[(r0 + 8) * 2] + rs[(r0 + 8) * 2 + 1]);
        #pragma unroll
        for (int nt = 0; nt < 8; nt++) {
            int col = 64 * wn2 + 8 * nt + 2 * tg;
            *(float2*)(ob + (size_t)r0 * DM + col) =
                make_float2(oc[mi][nt][0] * inv0, oc[mi][nt][1] * inv0);
            *(float2*)(ob + (size_t)(r0 + 8) * DM + col) =
                make_float2(oc[mi][nt][2] * inv1, oc[mi][nt][3] * inv1);
        }
    }
}

extern "C" void kernel_launch(void* const* d_in, const int* in_sizes, int n_in,
                              void* d_out, int out_size)
{
    const float* x   = (const float*)d_in[0];
    const float* wq  = (const float*)d_in[1];
    const float* bq  = (const float*)d_in[2];
    const float* wk  = (const float*)d_in[3];
    const float* bk  = (const float*)d_in[4];
    const float* wv  = (const float*)d_in[5];
    const float* bv  = (const float*)d_in[6];
    const float* pos = (const float*)d_in[7];
    float* out = (float*)d_out;

    cudaFuncSetAttribute(qkv_fused3, cudaFuncAttributeMaxDynamicSharedMemorySize,
                         QKV_SMEM);
    cudaFuncSetAttribute(attn_pipe64, cudaFuncAttributeMaxDynamicSharedMemorySize,
                         ATT_SMEM);

    wconv<<<192, 256>>>(wq, wk, wv);
    qkv_fused3<<<(NB * SEQ) / 128, 256, QKV_SMEM>>>(x, pos, bq, bk, bv);
    attn_pipe64<<<dim3(SEQ / 128, NB), 256, ATT_SMEM>>>(out);
}